// round 4
// baseline (speedup 1.0000x reference)
#include <cuda_runtime.h>

// Problem constants (from reference_code)
#define B_SZ      64
#define T_SZ      200
#define M_TOK     (B_SZ * T_SZ)   // 12800 tokens
#define D_SEM     768
#define D_PROMPT  384
#define K_DIM     (D_SEM + D_PROMPT)   // 1152
#define N_DIM     2048                  // d_model
#define NUM_ITEMS 100000

// GEMM tiling
#define BM   128
#define BN   128
#define BKT  16
#define PAD  4
#define NTHREADS 256

// C[m][n] = sum_k A[m][k] * W[n][k], A gathered on the fly:
//   A[m][k] = k < 768 ? E_sem[safe_id[m]][k] : v_prompt[safe_id[m]][k-768]
// Output masked to zero for invalid tokens.
__global__ __launch_bounds__(NTHREADS, 2)
void gemm_gather_kernel(const int*   __restrict__ ids,
                        const float* __restrict__ Esem,
                        const float* __restrict__ vpr,
                        const float* __restrict__ W,
                        float*       __restrict__ out)
{
    __shared__ float As[BKT][BM + PAD];
    __shared__ float Bs[BKT][BN];
    __shared__ int   s_id[BM];
    __shared__ int   s_valid[BM];

    const int tid = threadIdx.x;
    const int m0  = blockIdx.y * BM;
    const int n0  = blockIdx.x * BN;

    // Per-block token ids + validity (grid covers exactly M_TOK, no tail)
    if (tid < BM) {
        int id = ids[m0 + tid];
        int v  = (id >= 0) && (id < NUM_ITEMS);
        s_valid[tid] = v;
        s_id[tid]    = v ? id : 0;   // clamped gather, same as reference
    }
    __syncthreads();

    const int tx = tid & 15;   // 0..15  (N direction, 8 cols each)
    const int ty = tid >> 4;   // 0..15  (M direction, 8 rows each)

    float acc[8][8];
    #pragma unroll
    for (int i = 0; i < 8; i++)
        #pragma unroll
        for (int j = 0; j < 8; j++)
            acc[i][j] = 0.0f;

    // Tile-load decomposition: 128 rows x 16 cols = 512 float4; 2 per thread.
    // idx = tid + i*256 ; row = idx>>2 ; c4 = idx&3 (which float4 in the row)
    for (int kt = 0; kt < K_DIM; kt += BKT) {
        // ---- A tile (gathered) ----
        #pragma unroll
        for (int i = 0; i < 2; i++) {
            int idx = tid + i * NTHREADS;
            int row = idx >> 2;
            int c4  = idx & 3;
            int k   = kt + c4 * 4;              // 16B-aligned, never straddles 768
            int id  = s_id[row];
            const float* src = (k < D_SEM)
                ? (Esem + (long)id * D_SEM + k)
                : (vpr  + (long)id * D_PROMPT + (k - D_SEM));
            float4 v = *(const float4*)src;
            As[c4 * 4 + 0][row] = v.x;
            As[c4 * 4 + 1][row] = v.y;
            As[c4 * 4 + 2][row] = v.z;
            As[c4 * 4 + 3][row] = v.w;
        }
        // ---- W tile ----
        #pragma unroll
        for (int i = 0; i < 2; i++) {
            int idx = tid + i * NTHREADS;
            int row = idx >> 2;                 // local n
            int c4  = idx & 3;
            float4 v = *(const float4*)&W[(long)(n0 + row) * K_DIM + kt + c4 * 4];
            Bs[c4 * 4 + 0][row] = v.x;
            Bs[c4 * 4 + 1][row] = v.y;
            Bs[c4 * 4 + 2][row] = v.z;
            Bs[c4 * 4 + 3][row] = v.w;
        }
        __syncthreads();

        #pragma unroll
        for (int kk = 0; kk < BKT; kk++) {
            float a[8], b[8];
            *(float4*)&a[0] = *(const float4*)&As[kk][ty * 8];
            *(float4*)&a[4] = *(const float4*)&As[kk][ty * 8 + 4];
            *(float4*)&b[0] = *(const float4*)&Bs[kk][tx * 8];
            *(float4*)&b[4] = *(const float4*)&Bs[kk][tx * 8 + 4];
            #pragma unroll
            for (int i = 0; i < 8; i++)
                #pragma unroll
                for (int j = 0; j < 8; j++)
                    acc[i][j] = fmaf(a[i], b[j], acc[i][j]);
        }
        __syncthreads();
    }

    // Epilogue: masked, vectorized stores
    #pragma unroll
    for (int i = 0; i < 8; i++) {
        int   mrow  = ty * 8 + i;
        long  m     = m0 + mrow;
        float vmask = s_valid[mrow] ? 1.0f : 0.0f;
        #pragma unroll
        for (int j = 0; j < 8; j += 4) {
            float4 r;
            r.x = acc[i][j + 0] * vmask;
            r.y = acc[i][j + 1] * vmask;
            r.z = acc[i][j + 2] * vmask;
            r.w = acc[i][j + 3] * vmask;
            *(float4*)&out[m * N_DIM + n0 + tx * 8 + j] = r;
        }
    }
}

// amask [B,T] and tok_item_ids [B,T], written as floats after embeds.
__global__ void meta_kernel(const int* __restrict__ ids,
                            float* __restrict__ amask,
                            float* __restrict__ tok)
{
    int i = blockIdx.x * blockDim.x + threadIdx.x;
    if (i < M_TOK) {
        int id = ids[i];
        int v  = (id >= 0) && (id < NUM_ITEMS);
        amask[i] = v ? 1.0f : 0.0f;
        tok[i]   = v ? (float)id : -1.0f;
    }
}

extern "C" void kernel_launch(void* const* d_in, const int* in_sizes, int n_in,
                              void* d_out, int out_size)
{
    // metadata order: batch_item_ids_padded, batch_lengths, E_sem, v_prompt, proj_w
    const int*   ids  = (const int*)  d_in[0];
    // d_in[1] (batch_lengths) is unused: padding already encoded as -1 in ids
    const float* Esem = (const float*)d_in[2];
    const float* vpr  = (const float*)d_in[3];
    const float* W    = (const float*)d_in[4];
    float* out = (float*)d_out;

    dim3 grid(N_DIM / BN, M_TOK / BM);   // 16 x 100 blocks
    gemm_gather_kernel<<<grid, NTHREADS>>>(ids, Esem, vpr, W, out);

    const long embeds_elems = (long)M_TOK * N_DIM;           // 26,214,400
    if ((long)out_size >= embeds_elems + 2L * M_TOK) {
        float* amask = out + embeds_elems;
        float* tok   = amask + M_TOK;
        meta_kernel<<<(M_TOK + 255) / 256, 256>>>(ids, amask, tok);
    }
}

// round 7
// speedup vs baseline: 5.9276x; 5.9276x over previous
#include <cuda_runtime.h>
#include <stdint.h>

// ---------------- problem constants ----------------
#define M_TOK     12800
#define NUM_ITEMS 100000
#define D_SEM     768
#define D_PROMPT  384
#define KD        1152
#define ND        2048

// ---------------- tiling ----------------
#define BM        128
#define BN        128
#define KC        32               // K floats per chunk = 128B rows
#define NCHUNK    (KD / KC)        // 36
#define NTH       256              // 8 warps: 2 (M) x 4 (N), warptile 64x32
#define STAGEB    32768            // 16KB A + 16KB B
// dyn smem: 1024 align slack + 1024 control + 2 stages
#define SMEM_DYN  (1024 + 1024 + 2 * STAGEB)

__device__ __forceinline__ uint32_t smem_u32(const void* p) {
    uint32_t a;
    asm("{ .reg .u64 t; cvta.to.shared.u64 t, %1; cvt.u32.u64 %0, t; }"
        : "=r"(a) : "l"(p));
    return a;
}

// fp32 -> tf32 (round-to-nearest) -> swizzled shared store (16B)
__device__ __forceinline__ void sts_tf32(uint32_t a, float4 f) {
    uint32_t x, y, z, w;
    asm("cvt.rna.tf32.f32 %0, %1;" : "=r"(x) : "f"(f.x));
    asm("cvt.rna.tf32.f32 %0, %1;" : "=r"(y) : "f"(f.y));
    asm("cvt.rna.tf32.f32 %0, %1;" : "=r"(z) : "f"(f.z));
    asm("cvt.rna.tf32.f32 %0, %1;" : "=r"(w) : "f"(f.w));
    asm volatile("st.shared.v4.b32 [%0], {%1,%2,%3,%4};"
                 :: "r"(a), "r"(x), "r"(y), "r"(z), "r"(w) : "memory");
}

__device__ __forceinline__ void ldsm_x4(uint32_t a, uint32_t r[4]) {
    asm volatile("ldmatrix.sync.aligned.m8n8.x4.shared.b16 {%0,%1,%2,%3}, [%4];"
                 : "=r"(r[0]), "=r"(r[1]), "=r"(r[2]), "=r"(r[3]) : "r"(a));
}
__device__ __forceinline__ void ldsm_x2(uint32_t a, uint32_t r[2]) {
    asm volatile("ldmatrix.sync.aligned.m8n8.x2.shared.b16 {%0,%1}, [%2];"
                 : "=r"(r[0]), "=r"(r[1]) : "r"(a));
}
__device__ __forceinline__ void mma_tf32(float c[4], const uint32_t a[4], const uint32_t b[2]) {
    asm volatile("mma.sync.aligned.m16n8k8.row.col.f32.tf32.tf32.f32 "
                 "{%0,%1,%2,%3}, {%4,%5,%6,%7}, {%8,%9}, {%0,%1,%2,%3};"
                 : "+f"(c[0]), "+f"(c[1]), "+f"(c[2]), "+f"(c[3])
                 : "r"(a[0]), "r"(a[1]), "r"(a[2]), "r"(a[3]), "r"(b[0]), "r"(b[1]));
}

// gather one 128x32 A chunk slice + 128x32 W chunk slice into regs (per thread: 4+4 float4)
__device__ __forceinline__ void ld_chunk(int c,
                                         const float* const pE[4],
                                         const float* const pV[4],
                                         const float* const pW[4],
                                         float4 A[4], float4 Bv[4]) {
    #pragma unroll
    for (int p = 0; p < 4; p++) {
        const float* pa = (c < 24) ? (pE[p] + c * KC) : (pV[p] + (c - 24) * KC);
        A[p]  = *(const float4*)pa;
        Bv[p] = *(const float4*)(pW[p] + c * KC);
    }
}

__global__ __launch_bounds__(NTH, 1)
void fused_tf32_mma(const int*   __restrict__ ids,
                    const float* __restrict__ Esem,
                    const float* __restrict__ vpr,
                    const float* __restrict__ W,
                    float*       __restrict__ out)
{
    extern __shared__ char smraw[];
    const uint32_t sb0 = smem_u32(smraw);
    const uint32_t ab  = (sb0 + 1023u) & ~1023u;       // 1024-aligned
    char* sm = smraw + (ab - sb0);
    int* s_id  = (int*)(sm);                            // 128 ints
    int* s_val = (int*)(sm + 512);                      // 128 ints
    const uint32_t stage0 = ab + 1024;                  // stage s at +s*STAGEB; B at +16384

    const int tid  = threadIdx.x;
    const int wid  = tid >> 5;
    const int lane = tid & 31;
    const int m0   = blockIdx.y * BM;
    const int n0   = blockIdx.x * BN;

    if (tid < BM) {
        int id = ids[m0 + tid];
        int v  = (id >= 0) & (id < NUM_ITEMS);
        s_val[tid] = v;
        s_id[tid]  = v ? id : 0;
    }
    __syncthreads();

    // ---- producer addressing: thread covers rows rbase+32p, 16B granule kq ----
    const int kq    = tid & 7;
    const int rbase = tid >> 3;
    const float* pE[4]; const float* pV[4]; const float* pW[4];
    uint32_t swA[4], swB[4];                 // absolute stage-0 addresses
    #pragma unroll
    for (int p = 0; p < 4; p++) {
        int r  = rbase + 32 * p;
        int id = s_id[r];
        pE[p] = Esem + (size_t)id * D_SEM    + kq * 4;
        pV[p] = vpr  + (size_t)id * D_PROMPT + kq * 4;
        pW[p] = W    + (size_t)(n0 + r) * KD + kq * 4;
        uint32_t sw = (uint32_t)(r * 128 + ((kq ^ (r & 7)) << 4));
        swA[p] = stage0 + sw;
        swB[p] = stage0 + 16384 + sw;
    }

    // ---- consumer addressing (ldmatrix) ----
    // warp grid: 2 (M) x 4 (N); warptile 64x32
    const int wm = (wid & 1) * 64;
    const int wn = (wid >> 1) * 32;
    // A: x4 ldsm per (mtile, kstep). lane->row/granule mapping:
    //   q = lane>>3: q0: m+ (l&7), g+0 | q1: m+8+(l&7), g+0 | q2: m+(l&7), g+1 | q3: m+8+(l&7), g+1
    const int a_m  = wm + ((lane >> 3) & 1) * 8 + (lane & 7);   // + mt*16
    const uint32_t a_g = (uint32_t)(lane >> 4) << 4;            // granule offset *16
    uint32_t aRow[4], aX[4];
    #pragma unroll
    for (int mt = 0; mt < 4; mt++) {
        int m = a_m + mt * 16;
        aRow[mt] = stage0 + (uint32_t)(m * 128);
        aX[mt]   = (uint32_t)(m & 7) << 4;
    }
    // B: x2 ldsm per (ntile, kstep). lanes 0-7: n+(l&7), g+0 ; lanes 8-15: n+(l&7), g+1
    const int b_n  = wn + (lane & 7);                            // + nt*8
    const uint32_t b_g = (uint32_t)((lane >> 3) & 1) << 4;
    uint32_t bRow[4], bX[4];
    #pragma unroll
    for (int nt = 0; nt < 4; nt++) {
        int n = b_n + nt * 8;
        bRow[nt] = stage0 + 16384 + (uint32_t)(n * 128);
        bX[nt]   = (uint32_t)(n & 7) << 4;
    }

    float acc[4][4][4];
    #pragma unroll
    for (int mt = 0; mt < 4; mt++)
        #pragma unroll
        for (int nt = 0; nt < 4; nt++)
            #pragma unroll
            for (int r = 0; r < 4; r++) acc[mt][nt][r] = 0.0f;

    float4 bufA[4], bufB[4];
    ld_chunk(0, pE, pV, pW, bufA, bufB);

    for (int i = 0; i < NCHUNK; i++) {
        const uint32_t soff = (uint32_t)((i & 1) * STAGEB);
        // stage (i&1) was consumed in iter i-2; safe to overwrite (no barrier vs i-1's compute
        // which reads the other stage). Store chunk i:
        #pragma unroll
        for (int p = 0; p < 4; p++) {
            sts_tf32(swA[p] + soff, bufA[p]);
            sts_tf32(swB[p] + soff, bufB[p]);
        }
        if (i + 1 < NCHUNK)
            ld_chunk(i + 1, pE, pV, pW, bufA, bufB);   // overlaps compute below
        __syncthreads();                                // chunk i visible to all

        #pragma unroll
        for (int ks = 0; ks < 4; ks++) {
            const uint32_t kgA = ((uint32_t)(ks << 5) + a_g);
            const uint32_t kgB = ((uint32_t)(ks << 5) + b_g);
            uint32_t af[4][4], bf[4][2];
            #pragma unroll
            for (int mt = 0; mt < 4; mt++)
                ldsm_x4(aRow[mt] + soff + (kgA ^ aX[mt]), af[mt]);
            #pragma unroll
            for (int nt = 0; nt < 4; nt++)
                ldsm_x2(bRow[nt] + soff + (kgB ^ bX[nt]), bf[nt]);
            #pragma unroll
            for (int mt = 0; mt < 4; mt++)
                #pragma unroll
                for (int nt = 0; nt < 4; nt++)
                    mma_tf32(acc[mt][nt], af[mt], bf[nt]);
        }
    }

    // ---- epilogue: mask + store. c0,c1 -> (row g, cols 2q,2q+1); c2,c3 -> row g+8 ----
    const int g = lane >> 2;
    const int q = lane & 3;
    #pragma unroll
    for (int mt = 0; mt < 4; mt++) {
        const int r0 = wm + mt * 16 + g;
        const int r1 = r0 + 8;
        const float vm0 = s_val[r0] ? 1.0f : 0.0f;
        const float vm1 = s_val[r1] ? 1.0f : 0.0f;
        float* po0 = out + (size_t)(m0 + r0) * ND + n0 + wn + q * 2;
        float* po1 = out + (size_t)(m0 + r1) * ND + n0 + wn + q * 2;
        #pragma unroll
        for (int nt = 0; nt < 4; nt++) {
            float2 o0 = make_float2(acc[mt][nt][0] * vm0, acc[mt][nt][1] * vm0);
            float2 o1 = make_float2(acc[mt][nt][2] * vm1, acc[mt][nt][3] * vm1);
            *(float2*)(po0 + nt * 8) = o0;
            *(float2*)(po1 + nt * 8) = o1;
        }
    }
}

// ---------------- amask / tok_item_ids tail ----------------
__global__ void meta_kernel(const int* __restrict__ ids,
                            float* __restrict__ amask,
                            float* __restrict__ tok)
{
    int i = blockIdx.x * blockDim.x + threadIdx.x;
    if (i < M_TOK) {
        int id = ids[i];
        int v  = (id >= 0) && (id < NUM_ITEMS);
        amask[i] = v ? 1.0f : 0.0f;
        tok[i]   = v ? (float)id : -1.0f;
    }
}

extern "C" void kernel_launch(void* const* d_in, const int* in_sizes, int n_in,
                              void* d_out, int out_size)
{
    const int*   ids  = (const int*)  d_in[0];
    const float* Esem = (const float*)d_in[2];
    const float* vpr  = (const float*)d_in[3];
    const float* W    = (const float*)d_in[4];
    float* out = (float*)d_out;

    cudaFuncSetAttribute(fused_tf32_mma, cudaFuncAttributeMaxDynamicSharedMemorySize, SMEM_DYN);

    dim3 grid(ND / BN, M_TOK / BM);   // 16 x 100
    fused_tf32_mma<<<grid, NTH, SMEM_DYN>>>(ids, Esem, vpr, W, out);

    const long embeds_elems = (long)M_TOK * ND;
    if ((long)out_size >= embeds_elems + 2L * M_TOK) {
        float* amask = out + embeds_elems;
        float* tok   = amask + M_TOK;
        meta_kernel<<<(M_TOK + 255) / 256, 256>>>(ids, amask, tok);
    }
}